// round 5
// baseline (speedup 1.0000x reference)
#include <cuda_runtime.h>
#include <cuda_bf16.h>

// -----------------------------------------------------------------------------
// FrustumSegmentationNet — collapsed exact-math (R0 proof: FPS argmin always
// selects index 0 -> all groups identical -> axis-0 batchnorms collapse feats
// to the constant relu(be5)@Wd3^T + bd3). Output = per-pixel 6->80 linear with
// Kinv folded into per-channel (A,B,C) + folded bias, zero outside the box.
//
// R5: pixel-pair f32x2 packing (results memory-contiguous -> no unpacks,
// direct STG.128), broadcast-duplicated coefficient blob (4x LDS.128/channel),
// 64-bit AND boundary masks under uniform branch.
// -----------------------------------------------------------------------------

#define HWPIX 65536
#define NCH   80

// blob: per channel c, 16 floats (8 float2, each scalar duplicated):
// [A,A, B,B, C'',C'', w3,w3, w4,w4, w5,w5, bias,bias, 0,0]
// tail: [1280..1283] = box ints as float bits.  total 1296 floats.
#define BLOBF 1296
__device__ float g_pack[BLOBF];

typedef unsigned long long u64;

__device__ __forceinline__ u64 pk2(float x) {
    u64 r; asm("mov.b64 %0, {%1, %1};" : "=l"(r) : "f"(x)); return r;
}
__device__ __forceinline__ u64 pair2(float lo, float hi) {
    u64 r; asm("mov.b64 %0, {%1, %2};" : "=l"(r) : "f"(lo), "f"(hi)); return r;
}
__device__ __forceinline__ u64 fma2(u64 a, u64 b, u64 c) {
    u64 d; asm("fma.rn.f32x2 %0, %1, %2, %3;" : "=l"(d) : "l"(a), "l"(b), "l"(c));
    return d;
}

// ---- prep: constant-feats fold + duplicated coefficient packing ----------
__global__ __launch_bounds__(1024)
void frustum_prep_kernel(const float* __restrict__ be5,   // (256)
                         const float* __restrict__ Wd3,   // (128,256)
                         const float* __restrict__ bd3,   // (128)
                         const float* __restrict__ Ws,    // (80,134)
                         const float* __restrict__ bs,    // (80)
                         const float* __restrict__ intr,  // (3,3)
                         const int*   __restrict__ box)   // (5)
{
    __shared__ float sbe[256];
    __shared__ float sfc[128];
    __shared__ float sK[9];
    __shared__ float soff[2];

    const int t    = threadIdx.x;
    const int warp = t >> 5;
    const int lane = t & 31;

    if (t < 256) sbe[t] = fmaxf(be5[t], 0.0f);
    if (t == 0) {
        float a = intr[0], b = intr[1], c = intr[2];
        float d = intr[3], e = intr[4], f = intr[5];
        float g = intr[6], h = intr[7], i9 = intr[8];
        float det = a * (e * i9 - f * h) - b * (d * i9 - f * g) + c * (d * h - e * g);
        float inv = 1.0f / det;
        sK[0] = (e * i9 - f * h) * inv; sK[1] = (c * h - b * i9) * inv; sK[2] = (b * f - c * e) * inv;
        sK[3] = (f * g - d * i9) * inv; sK[4] = (a * i9 - c * g) * inv; sK[5] = (c * d - a * f) * inv;
        sK[6] = (d * h - e * g) * inv;  sK[7] = (b * g - a * h) * inv;  sK[8] = (a * e - b * d) * inv;
        soff[0] = 0.5f - (float)box[1];  // u offset
        soff[1] = 0.5f - (float)box[0];  // v offset
        g_pack[1280] = __int_as_float(box[0]);
        g_pack[1281] = __int_as_float(box[1]);
        g_pack[1282] = __int_as_float(box[2]);
        g_pack[1283] = __int_as_float(box[3]);
    }
    __syncthreads();

    // Phase 1: fc[j] = bd3[j] + relu(be5) . Wd3[j,:]; warp per row, coalesced.
    for (int j = warp; j < 128; j += 32) {
        const float4* row = reinterpret_cast<const float4*>(Wd3 + j * 256);
        float4 a = row[lane];
        float4 b = row[lane + 32];
        int k0 = 4 * lane, k1 = 128 + 4 * lane;
        float s = a.x * sbe[k0]     + a.y * sbe[k0 + 1]
                + a.z * sbe[k0 + 2] + a.w * sbe[k0 + 3]
                + b.x * sbe[k1]     + b.y * sbe[k1 + 1]
                + b.z * sbe[k1 + 2] + b.w * sbe[k1 + 3];
        #pragma unroll
        for (int off = 16; off > 0; off >>= 1)
            s += __shfl_down_sync(0xFFFFFFFFu, s, off);
        if (lane == 0) sfc[j] = bd3[j] + s;
    }
    __syncthreads();

    // Phase 2+3: warp per channel: bias fold + coefficient pack.
    for (int c = warp; c < NCH; c += 32) {
        const float* wsr = Ws + c * 134 + 6;
        float s = 0.0f;
        #pragma unroll
        for (int j = lane; j < 128; j += 32)
            s += sfc[j] * wsr[j];
        #pragma unroll
        for (int off = 16; off > 0; off >>= 1)
            s += __shfl_down_sync(0xFFFFFFFFu, s, off);
        if (lane == 0) {
            float bias = bs[c] + s;
            float w0 = Ws[c * 134 + 0], w1 = Ws[c * 134 + 1], w2 = Ws[c * 134 + 2];
            float w3 = Ws[c * 134 + 3], w4 = Ws[c * 134 + 4], w5 = Ws[c * 134 + 5];
            float A = w0 * sK[0] + w1 * sK[3] + w2 * sK[6];
            float B = w0 * sK[1] + w1 * sK[4] + w2 * sK[7];
            float C = w0 * sK[2] + w1 * sK[5] + w2 * sK[8]
                    + A * soff[0] + B * soff[1];
            float* dst = g_pack + c * 16;
            dst[0]  = A;    dst[1]  = A;
            dst[2]  = B;    dst[3]  = B;
            dst[4]  = C;    dst[5]  = C;
            dst[6]  = w3;   dst[7]  = w3;
            dst[8]  = w4;   dst[9]  = w4;
            dst[10] = w5;   dst[11] = w5;
            dst[12] = bias; dst[13] = bias;
            dst[14] = 0.0f; dst[15] = 0.0f;
        }
    }
}

// ---- seg: thread = (channel-group of 8, pixel quad); 640 x 256 -----------
__global__ __launch_bounds__(256)
void frustum_seg_kernel(const float* __restrict__ rgb,    // (H,W,3)
                        const float* __restrict__ depth,  // (H,W)
                        float* __restrict__ out)          // (80,H,W)
{
    __shared__ float sP[BLOBF];

    const int t = threadIdx.x;
    #pragma unroll
    for (int i = t; i < BLOBF / 4; i += 256)   // 324 float4
        reinterpret_cast<float4*>(sP)[i] =
            reinterpret_cast<const float4*>(g_pack)[i];
    __syncthreads();

    const int idx = blockIdx.x * 256 + t;     // 0 .. 163839
    const int g   = idx >> 14;                // channel group 0..9
    const int q   = idx & 16383;              // pixel quad
    const int p0  = q * 4;
    const int r   = p0 >> 8;
    const int cc0 = p0 & 255;

    // inputs (16B-aligned vector loads)
    float4 dz = *reinterpret_cast<const float4*>(depth + p0);
    const float4* rp = reinterpret_cast<const float4*>(rgb + (size_t)p0 * 3);
    float4 q0 = rp[0], q1 = rp[1], q2 = rp[2];

    // packed per-pixel-pair operands (lane0 = pixel i, lane1 = pixel i+1)
    u64 u01 = pair2((float)cc0,       (float)(cc0 + 1));
    u64 u23 = pair2((float)(cc0 + 2), (float)(cc0 + 3));
    u64 v2  = pk2((float)r);
    u64 z01 = pair2(dz.x, dz.y), z23 = pair2(dz.z, dz.w);
    u64 r01 = pair2(q0.x, q0.w), r23 = pair2(q1.z, q2.y);
    u64 g01 = pair2(q0.y, q1.x), g23 = pair2(q1.w, q2.z);
    u64 b01 = pair2(q0.z, q1.y), b23 = pair2(q2.x, q2.w);

    // boundary mask
    const int x1 = __float_as_int(sP[1280]);
    const int y1 = __float_as_int(sP[1281]);
    const int x2 = __float_as_int(sP[1282]);
    const int y2 = __float_as_int(sP[1283]);
    const bool rowin = (r >= x1) && (r < x2);
    bool in0 = rowin && (cc0     >= y1) && (cc0     < y2);
    bool in1 = rowin && (cc0 + 1 >= y1) && (cc0 + 1 < y2);
    bool in2 = rowin && (cc0 + 2 >= y1) && (cc0 + 2 < y2);
    bool in3 = rowin && (cc0 + 3 >= y1) && (cc0 + 3 < y2);
    const bool allin = in0 & in1 & in2 & in3;
    u64 m01 = 0, m23 = 0;
    if (!allin) {
        m01 = (in0 ? 0xFFFFFFFFull : 0ull) | (in1 ? 0xFFFFFFFF00000000ull : 0ull);
        m23 = (in2 ? 0xFFFFFFFFull : 0ull) | (in3 ? 0xFFFFFFFF00000000ull : 0ull);
    }

    float* outbase = out + (size_t)g * 8 * HWPIX + p0;

    #pragma unroll
    for (int cn = 0; cn < 8; cn++) {
        const float* cfp = sP + (g * 8 + cn) * 16;
        ulonglong2 c0 = *reinterpret_cast<const ulonglong2*>(cfp);      // A, B
        ulonglong2 c1 = *reinterpret_cast<const ulonglong2*>(cfp + 4);  // C, w3
        ulonglong2 c2 = *reinterpret_cast<const ulonglong2*>(cfp + 8);  // w4, w5
        ulonglong2 c3 = *reinterpret_cast<const ulonglong2*>(cfp + 12); // bias, 0

        u64 base = fma2(c0.y, v2, c1.x);            // B*v + C''
        u64 t01  = fma2(c0.x, u01, base);
        u64 t23  = fma2(c0.x, u23, base);

        u64 d01 = fma2(c2.y, b01, c3.x);            // w5*b + bias
        d01 = fma2(c2.x, g01, d01);                 // + w4*g
        d01 = fma2(c1.y, r01, d01);                 // + w3*r
        u64 d23 = fma2(c2.y, b23, c3.x);
        d23 = fma2(c2.x, g23, d23);
        d23 = fma2(c1.y, r23, d23);

        u64 s01 = fma2(z01, t01, d01);
        u64 s23 = fma2(z23, t23, d23);
        if (!allin) { s01 &= m01; s23 &= m23; }

        ulonglong2 o; o.x = s01; o.y = s23;
        *reinterpret_cast<ulonglong2*>(outbase + (size_t)cn * HWPIX) = o;
    }
}

extern "C" void kernel_launch(void* const* d_in, const int* in_sizes, int n_in,
                              void* d_out, int out_size)
{
    const float* rgb   = (const float*)d_in[0];
    const float* depth = (const float*)d_in[1];
    const float* intr  = (const float*)d_in[2];
    const int*   box   = (const int*)  d_in[3];
    const float* be5   = (const float*)d_in[23];
    const float* Wd3   = (const float*)d_in[24];
    const float* bd3   = (const float*)d_in[25];
    const float* Ws    = (const float*)d_in[26];
    const float* bs    = (const float*)d_in[27];
    float* out = (float*)d_out;

    frustum_prep_kernel<<<1, 1024>>>(be5, Wd3, bd3, Ws, bs, intr, box);
    frustum_seg_kernel<<<640, 256>>>(rgb, depth, out);
}

// round 7
// speedup vs baseline: 1.1622x; 1.1622x over previous
#include <cuda_runtime.h>
#include <cuda_bf16.h>

// -----------------------------------------------------------------------------
// FrustumSegmentationNet — collapsed exact-math, ONE kernel.
//
// R0 proof: FPS argmin always selects index 0 -> all 500 groups identical ->
// axis-0 batchnorms see zero variance -> feats = relu(be5) @ Wd3^T + bd3
// (constant). Output = per-pixel 6->80 linear with Kinv folded into per-channel
// (A,B,C), feats folded into per-channel bias; zero outside the box.
//
// R7 = R6 + 16B alignment fix: sP (LDS.128-accessed) and all shared arrays are
// explicitly __align__(16); R6 trapped because sK/soff (44B) pushed sP off
// 16B alignment.
// -----------------------------------------------------------------------------

#define HWPIX  65536
#define NCH    80
#define NITEMS 163840            // 16384 quads * 10 channel-groups
#define NBLK   148
#define IPB    1108              // ceil(NITEMS / NBLK)

typedef unsigned long long u64;

__device__ __forceinline__ u64 pk2(float x) {
    u64 r; asm("mov.b64 %0, {%1, %1};" : "=l"(r) : "f"(x)); return r;
}
__device__ __forceinline__ u64 pair2(float lo, float hi) {
    u64 r; asm("mov.b64 %0, {%1, %2};" : "=l"(r) : "f"(lo), "f"(hi)); return r;
}
__device__ __forceinline__ u64 fma2(u64 a, u64 b, u64 c) {
    u64 d; asm("fma.rn.f32x2 %0, %1, %2, %3;" : "=l"(d) : "l"(a), "l"(b), "l"(c));
    return d;
}

__global__ __launch_bounds__(1024, 1)
void frustum_all_kernel(const float* __restrict__ rgb,    // (H,W,3)
                        const float* __restrict__ depth,  // (H,W)
                        const float* __restrict__ intr,   // (3,3)
                        const int*   __restrict__ box,    // (5)
                        const float* __restrict__ be5,    // (256)
                        const float* __restrict__ Wd3,    // (128,256)
                        const float* __restrict__ bd3,    // (128)
                        const float* __restrict__ Ws,     // (80,134)
                        const float* __restrict__ bs,     // (80)
                        float* __restrict__ out)          // (80,H,W)
{
    // per-channel packed coefficients, duplicated scalars (LDS.128-accessed,
    // MUST be 16B aligned — declared first and explicitly aligned):
    // [A,A, B,B, C'',C'', w3,w3, w4,w4, w5,w5, bias,bias, 0,0] x 80
    __shared__ __align__(16) float sP[NCH * 16];
    __shared__ __align__(16) float sbe[256];
    __shared__ __align__(16) float sfc[128];
    __shared__ __align__(16) float sK[12];
    __shared__ __align__(16) float soff[4];
    __shared__ __align__(16) int   sbox[4];

    const int t    = threadIdx.x;
    const int warp = t >> 5;
    const int lane = t & 31;

    // ---- stage small constants ----
    if (t < 256) sbe[t] = fmaxf(be5[t], 0.0f);
    if (t == 0) {
        float a = intr[0], b = intr[1], c = intr[2];
        float d = intr[3], e = intr[4], f = intr[5];
        float g = intr[6], h = intr[7], i9 = intr[8];
        float det = a * (e * i9 - f * h) - b * (d * i9 - f * g) + c * (d * h - e * g);
        float inv = 1.0f / det;
        sK[0] = (e * i9 - f * h) * inv; sK[1] = (c * h - b * i9) * inv; sK[2] = (b * f - c * e) * inv;
        sK[3] = (f * g - d * i9) * inv; sK[4] = (a * i9 - c * g) * inv; sK[5] = (c * d - a * f) * inv;
        sK[6] = (d * h - e * g) * inv;  sK[7] = (b * g - a * h) * inv;  sK[8] = (a * e - b * d) * inv;
        int b0 = box[0], b1 = box[1], b2 = box[2], b3 = box[3];
        sbox[0] = b0; sbox[1] = b1; sbox[2] = b2; sbox[3] = b3;
        soff[0] = 0.5f - (float)b1;   // u offset (col)
        soff[1] = 0.5f - (float)b0;   // v offset (row)
    }
    __syncthreads();

    // ---- fc[j] = bd3[j] + relu(be5) . Wd3[j,:]; 32 warps x 4 rows each ----
    #pragma unroll
    for (int j = warp; j < 128; j += 32) {
        const float4* row = reinterpret_cast<const float4*>(Wd3 + j * 256);
        float4 a = row[lane];
        float4 b = row[lane + 32];
        int k0 = 4 * lane, k1 = 128 + 4 * lane;
        float s = a.x * sbe[k0]     + a.y * sbe[k0 + 1]
                + a.z * sbe[k0 + 2] + a.w * sbe[k0 + 3]
                + b.x * sbe[k1]     + b.y * sbe[k1 + 1]
                + b.z * sbe[k1 + 2] + b.w * sbe[k1 + 3];
        #pragma unroll
        for (int off = 16; off > 0; off >>= 1)
            s += __shfl_down_sync(0xFFFFFFFFu, s, off);
        if (lane == 0) sfc[j] = bd3[j] + s;
    }
    __syncthreads();

    // ---- per-channel bias + coefficient pack; warp per channel ----
    #pragma unroll
    for (int c = warp; c < NCH; c += 32) {
        const float* wsr = Ws + c * 134 + 6;
        float s = 0.0f;
        #pragma unroll
        for (int j = lane; j < 128; j += 32)
            s += sfc[j] * wsr[j];
        #pragma unroll
        for (int off = 16; off > 0; off >>= 1)
            s += __shfl_down_sync(0xFFFFFFFFu, s, off);
        if (lane == 0) {
            float bias = bs[c] + s;
            float w0 = Ws[c * 134 + 0], w1 = Ws[c * 134 + 1], w2 = Ws[c * 134 + 2];
            float w3 = Ws[c * 134 + 3], w4 = Ws[c * 134 + 4], w5 = Ws[c * 134 + 5];
            float A = w0 * sK[0] + w1 * sK[3] + w2 * sK[6];
            float B = w0 * sK[1] + w1 * sK[4] + w2 * sK[7];
            float C = w0 * sK[2] + w1 * sK[5] + w2 * sK[8]
                    + A * soff[0] + B * soff[1];
            float* dst = sP + c * 16;
            dst[0]  = A;    dst[1]  = A;
            dst[2]  = B;    dst[3]  = B;
            dst[4]  = C;    dst[5]  = C;
            dst[6]  = w3;   dst[7]  = w3;
            dst[8]  = w4;   dst[9]  = w4;
            dst[10] = w5;   dst[11] = w5;
            dst[12] = bias; dst[13] = bias;
            dst[14] = 0.0f; dst[15] = 0.0f;
        }
    }
    __syncthreads();

    const int x1 = sbox[0], y1 = sbox[1], x2 = sbox[2], y2 = sbox[3];

    // ---- pixel phase: contiguous item slice per block ----
    const int begin = blockIdx.x * IPB;
    int end = begin + IPB;
    if (end > NITEMS) end = NITEMS;

    for (int item = begin + t; item < end; item += 1024) {
        const int g   = item >> 14;          // channel group 0..9
        const int q   = item & 16383;        // pixel quad
        const int p0  = q * 4;
        const int r   = p0 >> 8;
        const int cc0 = p0 & 255;

        float4 dz = *reinterpret_cast<const float4*>(depth + p0);
        const float4* rp = reinterpret_cast<const float4*>(rgb + (size_t)p0 * 3);
        float4 q0 = rp[0], q1 = rp[1], q2 = rp[2];

        u64 u01 = pair2((float)cc0,       (float)(cc0 + 1));
        u64 u23 = pair2((float)(cc0 + 2), (float)(cc0 + 3));
        u64 v2  = pk2((float)r);
        u64 z01 = pair2(dz.x, dz.y), z23 = pair2(dz.z, dz.w);
        u64 r01 = pair2(q0.x, q0.w), r23 = pair2(q1.z, q2.y);
        u64 g01 = pair2(q0.y, q1.x), g23 = pair2(q1.w, q2.z);
        u64 b01 = pair2(q0.z, q1.y), b23 = pair2(q2.x, q2.w);

        const bool rowin = (r >= x1) && (r < x2);
        bool in0 = rowin && (cc0     >= y1) && (cc0     < y2);
        bool in1 = rowin && (cc0 + 1 >= y1) && (cc0 + 1 < y2);
        bool in2 = rowin && (cc0 + 2 >= y1) && (cc0 + 2 < y2);
        bool in3 = rowin && (cc0 + 3 >= y1) && (cc0 + 3 < y2);
        const bool allin = in0 & in1 & in2 & in3;
        u64 m01 = 0, m23 = 0;
        if (!allin) {
            m01 = (in0 ? 0xFFFFFFFFull : 0ull) | (in1 ? 0xFFFFFFFF00000000ull : 0ull);
            m23 = (in2 ? 0xFFFFFFFFull : 0ull) | (in3 ? 0xFFFFFFFF00000000ull : 0ull);
        }

        float* outbase = out + (size_t)g * 8 * HWPIX + p0;

        #pragma unroll
        for (int cn = 0; cn < 8; cn++) {
            const float* cfp = sP + (g * 8 + cn) * 16;
            ulonglong2 c0 = *reinterpret_cast<const ulonglong2*>(cfp);      // A, B
            ulonglong2 c1 = *reinterpret_cast<const ulonglong2*>(cfp + 4);  // C, w3
            ulonglong2 c2 = *reinterpret_cast<const ulonglong2*>(cfp + 8);  // w4, w5
            ulonglong2 c3 = *reinterpret_cast<const ulonglong2*>(cfp + 12); // bias, 0

            u64 base = fma2(c0.y, v2, c1.x);          // B*v + C''
            u64 t01  = fma2(c0.x, u01, base);
            u64 t23  = fma2(c0.x, u23, base);

            u64 d01 = fma2(c2.y, b01, c3.x);          // w5*b + bias
            d01 = fma2(c2.x, g01, d01);               // + w4*g
            d01 = fma2(c1.y, r01, d01);               // + w3*r
            u64 d23 = fma2(c2.y, b23, c3.x);
            d23 = fma2(c2.x, g23, d23);
            d23 = fma2(c1.y, r23, d23);

            u64 s01 = fma2(z01, t01, d01);
            u64 s23 = fma2(z23, t23, d23);
            if (!allin) { s01 &= m01; s23 &= m23; }

            ulonglong2 o; o.x = s01; o.y = s23;
            *reinterpret_cast<ulonglong2*>(outbase + (size_t)cn * HWPIX) = o;
        }
    }
}

extern "C" void kernel_launch(void* const* d_in, const int* in_sizes, int n_in,
                              void* d_out, int out_size)
{
    const float* rgb   = (const float*)d_in[0];
    const float* depth = (const float*)d_in[1];
    const float* intr  = (const float*)d_in[2];
    const int*   box   = (const int*)  d_in[3];
    const float* be5   = (const float*)d_in[23];
    const float* Wd3   = (const float*)d_in[24];
    const float* bd3   = (const float*)d_in[25];
    const float* Ws    = (const float*)d_in[26];
    const float* bs    = (const float*)d_in[27];
    float* out = (float*)d_out;

    frustum_all_kernel<<<NBLK, 1024>>>(rgb, depth, intr, box,
                                       be5, Wd3, bd3, Ws, bs, out);
}

// round 8
// speedup vs baseline: 1.1650x; 1.0025x over previous
#include <cuda_runtime.h>
#include <cuda_bf16.h>

// -----------------------------------------------------------------------------
// FrustumSegmentationNet — collapsed exact-math, ONE kernel, block-0 bias
// broadcast.
//
// R0 proof: FPS argmin always selects index 0 -> all groups identical ->
// axis-0 batchnorms collapse feats to the constant relu(be5)@Wd3^T + bd3.
// Output = per-pixel 6->80 linear with Kinv folded into per-channel (A,B,C),
// feats folded into per-channel bias; zero outside the box.
//
// R8: only block 0 does the 128KB Wd3 reduction (MLP-batched loads), publishes
// the 80 biases via global + release flag; all other blocks compute the cheap
// A/B/C coefficients, acquire-spin (~1us, overlapped), then run the R7 FFMA2
// pixel-pair body. Grid = 148 = one resident wave -> spin is deadlock-free.
// -----------------------------------------------------------------------------

#define HWPIX  65536
#define NCH    80
#define NITEMS 163840            // 16384 quads * 10 channel-groups
#define NBLK   148
#define IPB0   860               // block 0 slice (smaller: it also does prep)
#define IPBN   1109              // blocks 1..147: 860 + 147*1109 = 163883 >= NITEMS

typedef unsigned long long u64;

__device__ float g_bias[NCH];
__device__ int   g_flag = 0;

__device__ __forceinline__ u64 pk2(float x) {
    u64 r; asm("mov.b64 %0, {%1, %1};" : "=l"(r) : "f"(x)); return r;
}
__device__ __forceinline__ u64 pair2(float lo, float hi) {
    u64 r; asm("mov.b64 %0, {%1, %2};" : "=l"(r) : "f"(lo), "f"(hi)); return r;
}
__device__ __forceinline__ u64 fma2(u64 a, u64 b, u64 c) {
    u64 d; asm("fma.rn.f32x2 %0, %1, %2, %3;" : "=l"(d) : "l"(a), "l"(b), "l"(c));
    return d;
}
__device__ __forceinline__ int ld_acquire(const int* p) {
    int v; asm volatile("ld.global.acquire.gpu.b32 %0, [%1];" : "=r"(v) : "l"(p));
    return v;
}
__device__ __forceinline__ float warp_sum(float s) {
    #pragma unroll
    for (int off = 16; off > 0; off >>= 1)
        s += __shfl_down_sync(0xFFFFFFFFu, s, off);
    return s;
}

__global__ __launch_bounds__(1024, 1)
void frustum_all_kernel(const float* __restrict__ rgb,    // (H,W,3)
                        const float* __restrict__ depth,  // (H,W)
                        const float* __restrict__ intr,   // (3,3)
                        const int*   __restrict__ box,    // (5)
                        const float* __restrict__ be5,    // (256)
                        const float* __restrict__ Wd3,    // (128,256)
                        const float* __restrict__ bd3,    // (128)
                        const float* __restrict__ Ws,     // (80,134)
                        const float* __restrict__ bs,     // (80)
                        float* __restrict__ out)          // (80,H,W)
{
    // [A,A, B,B, C'',C'', w3,w3, w4,w4, w5,w5, bias,bias, 0,0] x 80
    __shared__ __align__(16) float sP[NCH * 16];
    __shared__ __align__(16) float sbe[256];
    __shared__ __align__(16) float sfc[128];
    __shared__ __align__(16) float sK[12];
    __shared__ __align__(16) float soff[4];
    __shared__ __align__(16) int   sbox[4];

    const int t    = threadIdx.x;
    const int warp = t >> 5;
    const int lane = t & 31;
    const int blk  = blockIdx.x;

    // ---- tiny shared constants (every block) ----
    if (t == 0) {
        float a = intr[0], b = intr[1], c = intr[2];
        float d = intr[3], e = intr[4], f = intr[5];
        float g = intr[6], h = intr[7], i9 = intr[8];
        float det = a * (e * i9 - f * h) - b * (d * i9 - f * g) + c * (d * h - e * g);
        float inv = 1.0f / det;
        sK[0] = (e * i9 - f * h) * inv; sK[1] = (c * h - b * i9) * inv; sK[2] = (b * f - c * e) * inv;
        sK[3] = (f * g - d * i9) * inv; sK[4] = (a * i9 - c * g) * inv; sK[5] = (c * d - a * f) * inv;
        sK[6] = (d * h - e * g) * inv;  sK[7] = (b * g - a * h) * inv;  sK[8] = (a * e - b * d) * inv;
        int b0 = box[0], b1 = box[1], b2 = box[2], b3 = box[3];
        sbox[0] = b0; sbox[1] = b1; sbox[2] = b2; sbox[3] = b3;
        soff[0] = 0.5f - (float)b1;   // u offset (col)
        soff[1] = 0.5f - (float)b0;   // v offset (row)
    }
    if (blk == 0 && t < 256) sbe[t] = fmaxf(be5[t], 0.0f);
    __syncthreads();

    // ---- cheap per-channel coefficients (every block) ----
    if (t < NCH) {
        float w0 = Ws[t * 134 + 0], w1 = Ws[t * 134 + 1], w2 = Ws[t * 134 + 2];
        float w3 = Ws[t * 134 + 3], w4 = Ws[t * 134 + 4], w5 = Ws[t * 134 + 5];
        float A = w0 * sK[0] + w1 * sK[3] + w2 * sK[6];
        float B = w0 * sK[1] + w1 * sK[4] + w2 * sK[7];
        float C = w0 * sK[2] + w1 * sK[5] + w2 * sK[8]
                + A * soff[0] + B * soff[1];
        float* dst = sP + t * 16;
        dst[0]  = A;  dst[1]  = A;
        dst[2]  = B;  dst[3]  = B;
        dst[4]  = C;  dst[5]  = C;
        dst[6]  = w3; dst[7]  = w3;
        dst[8]  = w4; dst[9]  = w4;
        dst[10] = w5; dst[11] = w5;
        dst[14] = 0.0f; dst[15] = 0.0f;
    }

    // ---- block 0 only: expensive bias reduction, MLP-batched ----
    if (blk == 0) {
        // phase 1: fc[j] for rows {warp, warp+32, warp+64, warp+96};
        // all 8 float4 loads issued before any reduction (MLP=8).
        {
            const float4* r0 = reinterpret_cast<const float4*>(Wd3 + (warp)      * 256);
            const float4* r1 = reinterpret_cast<const float4*>(Wd3 + (warp + 32) * 256);
            const float4* r2 = reinterpret_cast<const float4*>(Wd3 + (warp + 64) * 256);
            const float4* r3 = reinterpret_cast<const float4*>(Wd3 + (warp + 96) * 256);
            float4 a0 = r0[lane], b0v = r0[lane + 32];
            float4 a1 = r1[lane], b1v = r1[lane + 32];
            float4 a2 = r2[lane], b2v = r2[lane + 32];
            float4 a3 = r3[lane], b3v = r3[lane + 32];
            int k0 = 4 * lane, k1 = 128 + 4 * lane;
            float e0 = sbe[k0], e1 = sbe[k0 + 1], e2 = sbe[k0 + 2], e3 = sbe[k0 + 3];
            float f0 = sbe[k1], f1 = sbe[k1 + 1], f2 = sbe[k1 + 2], f3 = sbe[k1 + 3];
            float s0 = a0.x*e0 + a0.y*e1 + a0.z*e2 + a0.w*e3 + b0v.x*f0 + b0v.y*f1 + b0v.z*f2 + b0v.w*f3;
            float s1 = a1.x*e0 + a1.y*e1 + a1.z*e2 + a1.w*e3 + b1v.x*f0 + b1v.y*f1 + b1v.z*f2 + b1v.w*f3;
            float s2 = a2.x*e0 + a2.y*e1 + a2.z*e2 + a2.w*e3 + b2v.x*f0 + b2v.y*f1 + b2v.z*f2 + b2v.w*f3;
            float s3 = a3.x*e0 + a3.y*e1 + a3.z*e2 + a3.w*e3 + b3v.x*f0 + b3v.y*f1 + b3v.z*f2 + b3v.w*f3;
            s0 = warp_sum(s0); s1 = warp_sum(s1); s2 = warp_sum(s2); s3 = warp_sum(s3);
            if (lane == 0) {
                sfc[warp]      = bd3[warp]      + s0;
                sfc[warp + 32] = bd3[warp + 32] + s1;
                sfc[warp + 64] = bd3[warp + 64] + s2;
                sfc[warp + 96] = bd3[warp + 96] + s3;
            }
        }
        __syncthreads();

        // phase 2: biases; channels {warp, warp+32, (warp+64 if warp<16)};
        // all loads issued before reductions.
        {
            int c0 = warp, c1 = warp + 32, c2 = warp + 64;
            const float* p0 = Ws + c0 * 134 + 6;
            const float* p1 = Ws + c1 * 134 + 6;
            float w00 = p0[lane], w01 = p0[lane + 32], w02 = p0[lane + 64], w03 = p0[lane + 96];
            float w10 = p1[lane], w11 = p1[lane + 32], w12 = p1[lane + 64], w13 = p1[lane + 96];
            float w20 = 0.f, w21 = 0.f, w22 = 0.f, w23 = 0.f;
            if (warp < 16) {
                const float* p2 = Ws + c2 * 134 + 6;
                w20 = p2[lane]; w21 = p2[lane + 32]; w22 = p2[lane + 64]; w23 = p2[lane + 96];
            }
            float v0 = sfc[lane], v1 = sfc[lane + 32], v2 = sfc[lane + 64], v3 = sfc[lane + 96];
            float s0 = w00*v0 + w01*v1 + w02*v2 + w03*v3;
            float s1 = w10*v0 + w11*v1 + w12*v2 + w13*v3;
            float s2 = w20*v0 + w21*v1 + w22*v2 + w23*v3;
            s0 = warp_sum(s0); s1 = warp_sum(s1); s2 = warp_sum(s2);
            if (lane == 0) {
                g_bias[c0] = bs[c0] + s0;
                g_bias[c1] = bs[c1] + s1;
                if (warp < 16) g_bias[c2] = bs[c2] + s2;
            }
        }
        __syncthreads();
        if (t == 0) {
            __threadfence();
            atomicExch(&g_flag, 1);
        }
    } else {
        // acquire-spin; all 148 blocks are resident (one wave) -> safe.
        if (t == 0) {
            while (ld_acquire(&g_flag) == 0) { __nanosleep(32); }
        }
        __syncthreads();
    }

    // ---- fill bias slots ----
    if (t < NCH) {
        float b = g_bias[t];
        sP[t * 16 + 12] = b;
        sP[t * 16 + 13] = b;
    }
    __syncthreads();

    const int x1 = sbox[0], y1 = sbox[1], x2 = sbox[2], y2 = sbox[3];

    // ---- pixel phase: skewed contiguous slices (block 0 smaller) ----
    int begin, end;
    if (blk == 0) { begin = 0; end = IPB0; }
    else {
        begin = IPB0 + (blk - 1) * IPBN;
        end = begin + IPBN;
        if (end > NITEMS) end = NITEMS;
    }

    for (int item = begin + t; item < end; item += 1024) {
        const int g   = item >> 14;          // channel group 0..9
        const int q   = item & 16383;        // pixel quad
        const int p0  = q * 4;
        const int r   = p0 >> 8;
        const int cc0 = p0 & 255;

        float4 dz = *reinterpret_cast<const float4*>(depth + p0);
        const float4* rp = reinterpret_cast<const float4*>(rgb + (size_t)p0 * 3);
        float4 q0 = rp[0], q1 = rp[1], q2 = rp[2];

        u64 u01 = pair2((float)cc0,       (float)(cc0 + 1));
        u64 u23 = pair2((float)(cc0 + 2), (float)(cc0 + 3));
        u64 v2  = pk2((float)r);
        u64 z01 = pair2(dz.x, dz.y), z23 = pair2(dz.z, dz.w);
        u64 r01 = pair2(q0.x, q0.w), r23 = pair2(q1.z, q2.y);
        u64 g01 = pair2(q0.y, q1.x), g23 = pair2(q1.w, q2.z);
        u64 b01 = pair2(q0.z, q1.y), b23 = pair2(q2.x, q2.w);

        const bool rowin = (r >= x1) && (r < x2);
        bool in0 = rowin && (cc0     >= y1) && (cc0     < y2);
        bool in1 = rowin && (cc0 + 1 >= y1) && (cc0 + 1 < y2);
        bool in2 = rowin && (cc0 + 2 >= y1) && (cc0 + 2 < y2);
        bool in3 = rowin && (cc0 + 3 >= y1) && (cc0 + 3 < y2);
        const bool allin = in0 & in1 & in2 & in3;
        u64 m01 = 0, m23 = 0;
        if (!allin) {
            m01 = (in0 ? 0xFFFFFFFFull : 0ull) | (in1 ? 0xFFFFFFFF00000000ull : 0ull);
            m23 = (in2 ? 0xFFFFFFFFull : 0ull) | (in3 ? 0xFFFFFFFF00000000ull : 0ull);
        }

        float* outbase = out + (size_t)g * 8 * HWPIX + p0;

        #pragma unroll
        for (int cn = 0; cn < 8; cn++) {
            const float* cfp = sP + (g * 8 + cn) * 16;
            ulonglong2 c0 = *reinterpret_cast<const ulonglong2*>(cfp);      // A, B
            ulonglong2 c1 = *reinterpret_cast<const ulonglong2*>(cfp + 4);  // C, w3
            ulonglong2 c2 = *reinterpret_cast<const ulonglong2*>(cfp + 8);  // w4, w5
            ulonglong2 c3 = *reinterpret_cast<const ulonglong2*>(cfp + 12); // bias, 0

            u64 base = fma2(c0.y, v2, c1.x);          // B*v + C''
            u64 t01  = fma2(c0.x, u01, base);
            u64 t23  = fma2(c0.x, u23, base);

            u64 d01 = fma2(c2.y, b01, c3.x);          // w5*b + bias
            d01 = fma2(c2.x, g01, d01);               // + w4*g
            d01 = fma2(c1.y, r01, d01);               // + w3*r
            u64 d23 = fma2(c2.y, b23, c3.x);
            d23 = fma2(c2.x, g23, d23);
            d23 = fma2(c1.y, r23, d23);

            u64 s01 = fma2(z01, t01, d01);
            u64 s23 = fma2(z23, t23, d23);
            if (!allin) { s01 &= m01; s23 &= m23; }

            ulonglong2 o; o.x = s01; o.y = s23;
            *reinterpret_cast<ulonglong2*>(outbase + (size_t)cn * HWPIX) = o;
        }
    }
}

extern "C" void kernel_launch(void* const* d_in, const int* in_sizes, int n_in,
                              void* d_out, int out_size)
{
    const float* rgb   = (const float*)d_in[0];
    const float* depth = (const float*)d_in[1];
    const float* intr  = (const float*)d_in[2];
    const int*   box   = (const int*)  d_in[3];
    const float* be5   = (const float*)d_in[23];
    const float* Wd3   = (const float*)d_in[24];
    const float* bd3   = (const float*)d_in[25];
    const float* Ws    = (const float*)d_in[26];
    const float* bs    = (const float*)d_in[27];
    float* out = (float*)d_out;

    frustum_all_kernel<<<NBLK, 1024>>>(rgb, depth, intr, box,
                                       be5, Wd3, bd3, Ws, bs, out);
}